// round 2
// baseline (speedup 1.0000x reference)
#include <cuda_runtime.h>

// HEALPixPadding: [96,256,64,64] fp32, p=2 -> [96,256,68,68]
// Faces: nf = b*12 + f; f 0-3 north, 4-7 equatorial, 8-11 south.

constexpr int NPLANES   = 96 * 256;          // (nf, ch) planes = 24576
constexpr int PLANE_IN  = 64 * 64;           // 4096
constexpr int PLANE_OUT = 68 * 68;           // 4624
constexpr unsigned NB_INT = 196608;          // NPLANES*64*32 float2 / 256
constexpr int N_BORDER  = NPLANES * 528;     // 12,976,128 border elements
constexpr unsigned NB_BORDER = (unsigned)(N_BORDER / 256);  // 50688 (exact)

__global__ void __launch_bounds__(256) hpx_pad_kernel(const float* __restrict__ in,
                                                      float* __restrict__ out)
{
    unsigned bid = blockIdx.x;

    if (bid < NB_INT) {
        // ---------------- interior copy: out[...,2:66,2:66] = in ----------------
        unsigned t     = bid * 256u + threadIdx.x;    // float2 element index
        unsigned col2  = t & 31u;                     // 0..31 (pairs of floats)
        unsigned row   = (t >> 5) & 63u;              // 0..63
        unsigned plane = t >> 11;                     // 0..24575
        float2 v = reinterpret_cast<const float2*>(in)[plane * 2048u + row * 32u + col2];
        // float offset = plane*4624 + (row+2)*68 + 2 + 2*col2  (even)
        unsigned o2 = plane * 2312u + (row + 2u) * 34u + 1u + col2;
        reinterpret_cast<float2*>(out)[o2] = v;
        return;
    }

    // ---------------- border gather ----------------
    unsigned e = (bid - NB_INT) * 256u + threadIdx.x;
    if (e >= (unsigned)N_BORDER) return;

    unsigned plane = e / 528u;
    unsigned k     = e - plane * 528u;
    unsigned nf    = plane >> 8;          // /256
    unsigned ch    = plane & 255u;
    unsigned bb    = nf / 12u;
    int      f     = (int)(nf - bb * 12u);

    // k -> (r,c) over border positions of the 68x68 tile
    int r, c;
    if (k < 136u) {                       // top 2 rows
        r = (int)(k / 68u); c = (int)(k - (unsigned)r * 68u);
    } else if (k < 272u) {                // bottom 2 rows
        unsigned m = k - 136u;
        int mr = (int)(m / 68u);
        r = 66 + mr; c = (int)(m - (unsigned)mr * 68u);
    } else {                              // side columns, rows 2..65
        unsigned m = k - 272u;
        r = 2 + (int)(m >> 2);
        int q = (int)(m & 3u);
        c = (q < 2) ? q : q + 64;         // 0,1,66,67
    }

    int typ = f >> 2;        // 0=north 1=eq 2=south
    int n   = f & 3;

    // neighbor faces
    int ft, ftl, flf, fbl, fbo, fbr, frg, ftr;
    if (typ == 0) {
        ft  = (n + 1) & 3;  ftl = (n + 2) & 3;  flf = (n + 3) & 3;  fbl = flf;
        fbo = n + 4;        fbr = n + 8;        frg = ((n + 1) & 3) + 4;  ftr = ft;
    } else if (typ == 1) {
        ft  = n;            flf = (n + 3) & 3;  fbl = ((n + 3) & 3) + 4;
        fbo = ((n + 3) & 3) + 8;  frg = n + 8;  ftr = ((n + 1) & 3) + 4;
        ftl = -1; fbr = -1;  // synthesized corners
    } else {
        ft  = ((n + 1) & 3) + 4;  ftl = n;  flf = n + 4;
        fbl = ((n + 3) & 3) + 8;  fbo = fbl;
        fbr = ((n + 2) & 3) + 8;  frg = ((n + 1) & 3) + 8;  ftr = frg;
    }

    int rg_r = (r < 2) ? 0 : (r < 66 ? 1 : 2);
    int rg_c = (c < 2) ? 0 : (c < 66 ? 1 : 2);
    int reg  = rg_r * 3 + rg_c;

    int sf0 = 0, sr0 = 0, sc0 = 0;
    int sf1 = -1, sr1 = 0, sc1 = 0;

    switch (reg) {
    case 0:  // top-left
        if (typ == 0)      { sf0 = ftl; sr0 = 1 - r;   sc0 = 1 - c; }
        else if (typ == 2) { sf0 = ftl; sr0 = 62 + r;  sc0 = 62 + c; }
        else {             // eq: synthesized _tl(t, lft)
            if (c > r)      { sf0 = ft;  sr0 = 62 + r;     sc0 = c - r - 1; }
            else if (c < r) { sf0 = flf; sr0 = r - c - 1;  sc0 = 62 + c; }
            else            { sf0 = ft;  sr0 = 62 + r;  sc0 = 0;
                              sf1 = flf; sr1 = 0;       sc1 = 62 + r; }
        }
        break;
    case 1:  // top-mid
        if (typ == 0) { sf0 = ft; sr0 = c - 2;  sc0 = 1 - r; }
        else          { sf0 = ft; sr0 = 62 + r; sc0 = c - 2; }
        break;
    case 2:  // top-right (same for all types)
        sf0 = ftr; sr0 = 62 + r; sc0 = c - 66;
        break;
    case 3:  // mid-left
        if (typ == 0) { sf0 = flf; sr0 = 1 - c;  sc0 = r - 2; }
        else          { sf0 = flf; sr0 = r - 2;  sc0 = 62 + c; }
        break;
    case 5:  // mid-right
        if (typ == 2) { sf0 = frg; sr0 = 129 - c; sc0 = r - 2; }
        else          { sf0 = frg; sr0 = r - 2;   sc0 = c - 66; }
        break;
    case 6:  // bottom-left (same for all types)
        sf0 = fbl; sr0 = r - 66; sc0 = 62 + c;
        break;
    case 7:  // bottom-mid
        if (typ == 2) { sf0 = fbo; sr0 = c - 2;  sc0 = 129 - r; }
        else          { sf0 = fbo; sr0 = r - 66; sc0 = c - 2; }
        break;
    default: // case 8: bottom-right
        if (typ == 0)      { sf0 = fbr; sr0 = r - 66;  sc0 = c - 66; }
        else if (typ == 2) { sf0 = fbr; sr0 = 129 - r; sc0 = 129 - c; }
        else {             // eq: synthesized _br(b, rgt)
            int rr = r - 66, cc = c - 66;
            if (cc < rr)      { sf0 = fbo; sr0 = rr;            sc0 = 64 - rr + cc; }
            else if (cc > rr) { sf0 = frg; sr0 = 64 - cc + rr;  sc0 = cc; }
            else              { sf0 = fbo; sr0 = rr; sc0 = 63;
                                sf1 = frg; sr1 = 63; sc1 = rr; }
        }
        break;
    }

    unsigned srcBase = (bb * 12u) * 256u + ch;   // (b*12 + face)*256 + ch, face added below
    unsigned i0 = (srcBase + (unsigned)sf0 * 256u) * (unsigned)PLANE_IN
                + (unsigned)(sr0 * 64 + sc0);
    float v = __ldg(in + i0);
    if (sf1 >= 0) {
        unsigned i1 = (srcBase + (unsigned)sf1 * 256u) * (unsigned)PLANE_IN
                    + (unsigned)(sr1 * 64 + sc1);
        v = 0.5f * v + 0.5f * __ldg(in + i1);
    }
    out[plane * (unsigned)PLANE_OUT + (unsigned)(r * 68 + c)] = v;
}

extern "C" void kernel_launch(void* const* d_in, const int* in_sizes, int n_in,
                              void* d_out, int out_size)
{
    const float* in = (const float*)d_in[0];
    float* out = (float*)d_out;
    hpx_pad_kernel<<<NB_INT + NB_BORDER, 256>>>(in, out);
}

// round 3
// speedup vs baseline: 1.2050x; 1.2050x over previous
#include <cuda_runtime.h>

// HEALPixPadding fused: [8*12, 256, 64, 64] fp32, p=2 -> [96, 256, 68, 68]
// One block per (batch, channel): copies interiors of all 12 faces, deposits
// halo lines (rows/cols 0,1,62,63) to smem during the copy, then computes all
// border cells from smem. No redundant global reads.

constexpr int PLANE_IN_F4 = 1024;   // 64*64/4
constexpr int PLANE_OUT   = 4624;   // 68*68

// smem line ids: 0=row0 1=row1 2=row62 3=row63 4=col0 5=col1 6=col62 7=col63
__device__ __forceinline__ float hfetch(const float sm[12][8][64], int f, int r, int c)
{
    if (r < 2 || r >= 62) {
        int line = (r & 1) | ((r >= 62) ? 2 : 0);
        return sm[f][line][c];
    } else {
        int line = 4 + ((c & 1) | ((c >= 62) ? 2 : 0));
        return sm[f][line][r];
    }
}

__global__ void __launch_bounds__(256) hpx_pad_fused(const float* __restrict__ in,
                                                     float* __restrict__ out)
{
    __shared__ float sm[12][8][64];   // 24 KB

    const unsigned tid = threadIdx.x;
    const unsigned blk = blockIdx.x;       // 0..2047
    const unsigned bb  = blk >> 8;         // 0..7
    const unsigned ch  = blk & 255u;
    const unsigned planeBase = bb * 12u * 256u + ch;   // + face*256

    // ---------- Phase 1: interior copy + halo deposit ----------
    #pragma unroll 4
    for (unsigned i = tid; i < 12u * PLANE_IN_F4; i += 256u) {
        unsigned face = i >> 10;
        unsigned rem  = i & 1023u;
        unsigned row  = rem >> 4;          // 0..63
        unsigned qc   = rem & 15u;         // float4 index within row
        unsigned plane = planeBase + face * 256u;

        float4 v = reinterpret_cast<const float4*>(in)[plane * 1024u + row * 16u + qc];

        // out interior offset = plane*4624 + (row+2)*68 + 2 + qc*4  (== 2 mod 4 -> 8B aligned)
        unsigned ob = plane * (unsigned)PLANE_OUT + (row + 2u) * 68u + 2u + qc * 4u;
        float2* o2 = reinterpret_cast<float2*>(out + ob);
        o2[0] = make_float2(v.x, v.y);
        o2[1] = make_float2(v.z, v.w);

        if (row < 2u || row >= 62u) {
            unsigned line = (row & 1u) | ((row >= 62u) ? 2u : 0u);
            unsigned cb = qc * 4u;
            sm[face][line][cb + 0] = v.x;
            sm[face][line][cb + 1] = v.y;
            sm[face][line][cb + 2] = v.z;
            sm[face][line][cb + 3] = v.w;
        }
        if (qc == 0u)  { sm[face][4][row] = v.x; sm[face][5][row] = v.y; }
        if (qc == 15u) { sm[face][6][row] = v.z; sm[face][7][row] = v.w; }
    }

    __syncthreads();

    // ---------- Phase 2: border cells (12 faces x 528) ----------
    for (unsigned e = tid; e < 12u * 528u; e += 256u) {
        unsigned fu = e / 528u;
        unsigned k  = e - fu * 528u;
        int f = (int)fu;

        // k -> (r,c) over border of 68x68 tile
        int r, c;
        if (k < 136u) {                       // top 2 rows
            r = (int)(k / 68u); c = (int)(k - (unsigned)r * 68u);
        } else if (k < 272u) {                // bottom 2 rows
            unsigned m = k - 136u;
            int mr = (int)(m / 68u);
            r = 66 + mr; c = (int)(m - (unsigned)mr * 68u);
        } else {                              // side columns, rows 2..65
            unsigned m = k - 272u;
            r = 2 + (int)(m >> 2);
            int q = (int)(m & 3u);
            c = (q < 2) ? q : q + 64;
        }

        int typ = f >> 2;        // 0=north 1=eq 2=south
        int n   = f & 3;

        int ft, ftl, flf, fbl, fbo, fbr, frg, ftr;
        if (typ == 0) {
            ft  = (n + 1) & 3;  ftl = (n + 2) & 3;  flf = (n + 3) & 3;  fbl = flf;
            fbo = n + 4;        fbr = n + 8;        frg = ((n + 1) & 3) + 4;  ftr = ft;
        } else if (typ == 1) {
            ft  = n;            flf = (n + 3) & 3;  fbl = ((n + 3) & 3) + 4;
            fbo = ((n + 3) & 3) + 8;  frg = n + 8;  ftr = ((n + 1) & 3) + 4;
            ftl = -1; fbr = -1;
        } else {
            ft  = ((n + 1) & 3) + 4;  ftl = n;  flf = n + 4;
            fbl = ((n + 3) & 3) + 8;  fbo = fbl;
            fbr = ((n + 2) & 3) + 8;  frg = ((n + 1) & 3) + 8;  ftr = frg;
        }

        int rg_r = (r < 2) ? 0 : (r < 66 ? 1 : 2);
        int rg_c = (c < 2) ? 0 : (c < 66 ? 1 : 2);
        int reg  = rg_r * 3 + rg_c;

        int sf0 = 0, sr0 = 0, sc0 = 0;
        int sf1 = -1, sr1 = 0, sc1 = 0;

        switch (reg) {
        case 0:  // top-left
            if (typ == 0)      { sf0 = ftl; sr0 = 1 - r;   sc0 = 1 - c; }
            else if (typ == 2) { sf0 = ftl; sr0 = 62 + r;  sc0 = 62 + c; }
            else {
                if (c > r)      { sf0 = ft;  sr0 = 62 + r;     sc0 = c - r - 1; }
                else if (c < r) { sf0 = flf; sr0 = r - c - 1;  sc0 = 62 + c; }
                else            { sf0 = ft;  sr0 = 62 + r;  sc0 = 0;
                                  sf1 = flf; sr1 = 0;       sc1 = 62 + r; }
            }
            break;
        case 1:  // top-mid
            if (typ == 0) { sf0 = ft; sr0 = c - 2;  sc0 = 1 - r; }
            else          { sf0 = ft; sr0 = 62 + r; sc0 = c - 2; }
            break;
        case 2:  // top-right
            sf0 = ftr; sr0 = 62 + r; sc0 = c - 66;
            break;
        case 3:  // mid-left
            if (typ == 0) { sf0 = flf; sr0 = 1 - c;  sc0 = r - 2; }
            else          { sf0 = flf; sr0 = r - 2;  sc0 = 62 + c; }
            break;
        case 5:  // mid-right
            if (typ == 2) { sf0 = frg; sr0 = 129 - c; sc0 = r - 2; }
            else          { sf0 = frg; sr0 = r - 2;   sc0 = c - 66; }
            break;
        case 6:  // bottom-left
            sf0 = fbl; sr0 = r - 66; sc0 = 62 + c;
            break;
        case 7:  // bottom-mid
            if (typ == 2) { sf0 = fbo; sr0 = c - 2;  sc0 = 129 - r; }
            else          { sf0 = fbo; sr0 = r - 66; sc0 = c - 2; }
            break;
        default: // bottom-right
            if (typ == 0)      { sf0 = fbr; sr0 = r - 66;  sc0 = c - 66; }
            else if (typ == 2) { sf0 = fbr; sr0 = 129 - r; sc0 = 129 - c; }
            else {
                int rr = r - 66, cc = c - 66;
                if (cc < rr)      { sf0 = fbo; sr0 = rr;            sc0 = 64 - rr + cc; }
                else if (cc > rr) { sf0 = frg; sr0 = 64 - cc + rr;  sc0 = cc; }
                else              { sf0 = fbo; sr0 = rr; sc0 = 63;
                                    sf1 = frg; sr1 = 63; sc1 = rr; }
            }
            break;
        }

        float v = hfetch(sm, sf0, sr0, sc0);
        if (sf1 >= 0)
            v = 0.5f * v + 0.5f * hfetch(sm, sf1, sr1, sc1);

        out[(planeBase + fu * 256u) * (unsigned)PLANE_OUT + (unsigned)(r * 68 + c)] = v;
    }
}

extern "C" void kernel_launch(void* const* d_in, const int* in_sizes, int n_in,
                              void* d_out, int out_size)
{
    const float* in = (const float*)d_in[0];
    float* out = (float*)d_out;
    hpx_pad_fused<<<2048, 256>>>(in, out);
}

// round 4
// speedup vs baseline: 1.2405x; 1.0295x over previous
#include <cuda_runtime.h>

// HEALPixPadding fused: [8*12, 256, 64, 64] fp32, p=2 -> [96, 256, 68, 68]
// One block per (batch, channel). Phase 1: interior copy + halo-line deposit
// to smem. Phase 2: table-driven border gather from smem (table precomputed
// by a tiny init kernel each launch; identical across blocks, L1-hot).

constexpr int PLANE_OUT = 4624;     // 68*68
constexpr int NBORDER   = 12 * 528; // 6336 border cells per (b,ch)

// table entry: .x = face*256*4624 + r*68 + c (output offset within group)
//              .y = src0 (13b) | src1 (13b) << 13 | blend (1b) << 26
__device__ uint2 hpx_tab[NBORDER];

// smem flat index: f*512 + line*64 + idx
// lines: 0=row0 1=row1 2=row62 3=row63 4=col0 5=col1 6=col62 7=col63
__host__ __device__ __forceinline__ int hidx(int f, int r, int c)
{
    int line, idx;
    if (r < 2 || r >= 62) { line = (r & 1) | ((r >= 62) ? 2 : 0); idx = c; }
    else                  { line = 4 + ((c & 1) | ((c >= 62) ? 2 : 0)); idx = r; }
    return f * 512 + line * 64 + idx;
}

__global__ void __launch_bounds__(256) hpx_build_tab()
{
    int e = blockIdx.x * 256 + threadIdx.x;
    if (e >= NBORDER) return;

    int f = e / 528;
    unsigned k = (unsigned)(e - f * 528);

    int r, c;
    if (k < 136u) {
        r = (int)(k / 68u); c = (int)(k - (unsigned)r * 68u);
    } else if (k < 272u) {
        unsigned m = k - 136u;
        int mr = (int)(m / 68u);
        r = 66 + mr; c = (int)(m - (unsigned)mr * 68u);
    } else {
        unsigned m = k - 272u;
        r = 2 + (int)(m >> 2);
        int q = (int)(m & 3u);
        c = (q < 2) ? q : q + 64;
    }

    int typ = f >> 2, n = f & 3;
    int ft, ftl, flf, fbl, fbo, fbr, frg, ftr;
    if (typ == 0) {
        ft  = (n + 1) & 3;  ftl = (n + 2) & 3;  flf = (n + 3) & 3;  fbl = flf;
        fbo = n + 4;        fbr = n + 8;        frg = ((n + 1) & 3) + 4;  ftr = ft;
    } else if (typ == 1) {
        ft  = n;            flf = (n + 3) & 3;  fbl = ((n + 3) & 3) + 4;
        fbo = ((n + 3) & 3) + 8;  frg = n + 8;  ftr = ((n + 1) & 3) + 4;
        ftl = -1; fbr = -1;
    } else {
        ft  = ((n + 1) & 3) + 4;  ftl = n;  flf = n + 4;
        fbl = ((n + 3) & 3) + 8;  fbo = fbl;
        fbr = ((n + 2) & 3) + 8;  frg = ((n + 1) & 3) + 8;  ftr = frg;
    }

    int rg_r = (r < 2) ? 0 : (r < 66 ? 1 : 2);
    int rg_c = (c < 2) ? 0 : (c < 66 ? 1 : 2);
    int reg  = rg_r * 3 + rg_c;

    int sf0 = 0, sr0 = 0, sc0 = 0;
    int sf1 = -1, sr1 = 0, sc1 = 0;

    switch (reg) {
    case 0:
        if (typ == 0)      { sf0 = ftl; sr0 = 1 - r;   sc0 = 1 - c; }
        else if (typ == 2) { sf0 = ftl; sr0 = 62 + r;  sc0 = 62 + c; }
        else {
            if (c > r)      { sf0 = ft;  sr0 = 62 + r;     sc0 = c - r - 1; }
            else if (c < r) { sf0 = flf; sr0 = r - c - 1;  sc0 = 62 + c; }
            else            { sf0 = ft;  sr0 = 62 + r;  sc0 = 0;
                              sf1 = flf; sr1 = 0;       sc1 = 62 + r; }
        }
        break;
    case 1:
        if (typ == 0) { sf0 = ft; sr0 = c - 2;  sc0 = 1 - r; }
        else          { sf0 = ft; sr0 = 62 + r; sc0 = c - 2; }
        break;
    case 2:
        sf0 = ftr; sr0 = 62 + r; sc0 = c - 66;
        break;
    case 3:
        if (typ == 0) { sf0 = flf; sr0 = 1 - c;  sc0 = r - 2; }
        else          { sf0 = flf; sr0 = r - 2;  sc0 = 62 + c; }
        break;
    case 5:
        if (typ == 2) { sf0 = frg; sr0 = 129 - c; sc0 = r - 2; }
        else          { sf0 = frg; sr0 = r - 2;   sc0 = c - 66; }
        break;
    case 6:
        sf0 = fbl; sr0 = r - 66; sc0 = 62 + c;
        break;
    case 7:
        if (typ == 2) { sf0 = fbo; sr0 = c - 2;  sc0 = 129 - r; }
        else          { sf0 = fbo; sr0 = r - 66; sc0 = c - 2; }
        break;
    default:
        if (typ == 0)      { sf0 = fbr; sr0 = r - 66;  sc0 = c - 66; }
        else if (typ == 2) { sf0 = fbr; sr0 = 129 - r; sc0 = 129 - c; }
        else {
            int rr = r - 66, cc = c - 66;
            if (cc < rr)      { sf0 = fbo; sr0 = rr;            sc0 = 64 - rr + cc; }
            else if (cc > rr) { sf0 = frg; sr0 = 64 - cc + rr;  sc0 = cc; }
            else              { sf0 = fbo; sr0 = rr; sc0 = 63;
                                sf1 = frg; sr1 = 63; sc1 = rr; }
        }
        break;
    }

    uint2 t;
    t.x = (unsigned)(f * 256 * PLANE_OUT + r * 68 + c);
    t.y = (unsigned)hidx(sf0, sr0, sc0);
    if (sf1 >= 0)
        t.y |= ((unsigned)hidx(sf1, sr1, sc1) << 13) | (1u << 26);
    hpx_tab[e] = t;
}

__global__ void __launch_bounds__(256, 8) hpx_pad_fused(const float* __restrict__ in,
                                                        float* __restrict__ out)
{
    __shared__ float sm[12 * 8 * 64];   // 24 KB

    const unsigned tid = threadIdx.x;
    const unsigned blk = blockIdx.x;       // 0..2047
    const unsigned bb  = blk >> 8;
    const unsigned ch  = blk & 255u;
    const unsigned planeBase = bb * 3072u + ch;   // (b*12+face)*256+ch minus face term

    // ---------- Phase 1: interior copy + halo deposit ----------
    #pragma unroll 4
    for (unsigned i = tid; i < 12u * 1024u; i += 256u) {
        unsigned face = i >> 10;
        unsigned rem  = i & 1023u;
        unsigned row  = rem >> 4;
        unsigned qc   = rem & 15u;
        unsigned plane = planeBase + face * 256u;

        float4 v = reinterpret_cast<const float4*>(in)[plane * 1024u + row * 16u + qc];

        unsigned ob = plane * (unsigned)PLANE_OUT + (row + 2u) * 68u + 2u + qc * 4u;
        float2* o2 = reinterpret_cast<float2*>(out + ob);
        o2[0] = make_float2(v.x, v.y);
        o2[1] = make_float2(v.z, v.w);

        if (row < 2u || row >= 62u) {
            unsigned line = (row & 1u) | ((row >= 62u) ? 2u : 0u);
            unsigned b0 = face * 512u + line * 64u + qc * 4u;
            sm[b0 + 0] = v.x; sm[b0 + 1] = v.y; sm[b0 + 2] = v.z; sm[b0 + 3] = v.w;
        }
        if (qc == 0u)  { sm[face * 512u + 4u * 64u + row] = v.x;
                         sm[face * 512u + 5u * 64u + row] = v.y; }
        if (qc == 15u) { sm[face * 512u + 6u * 64u + row] = v.z;
                         sm[face * 512u + 7u * 64u + row] = v.w; }
    }

    __syncthreads();

    // ---------- Phase 2: table-driven border ----------
    const unsigned outBase = planeBase * (unsigned)PLANE_OUT;
    #pragma unroll 4
    for (unsigned e = tid; e < (unsigned)NBORDER; e += 256u) {
        uint2 t = __ldg(&hpx_tab[e]);
        float v = sm[t.y & 8191u];
        if (t.y >> 26)
            v = 0.5f * v + 0.5f * sm[(t.y >> 13) & 8191u];
        out[outBase + t.x] = v;
    }
}

extern "C" void kernel_launch(void* const* d_in, const int* in_sizes, int n_in,
                              void* d_out, int out_size)
{
    const float* in = (const float*)d_in[0];
    float* out = (float*)d_out;
    hpx_build_tab<<<(NBORDER + 255) / 256, 256>>>();
    hpx_pad_fused<<<2048, 256>>>(in, out);
}

// round 9
// speedup vs baseline: 1.9692x; 1.5875x over previous
#include <cuda_runtime.h>

// HEALPixPadding: [8*12, 256, 64, 64] fp32, p=2 -> [96, 256, 68, 68]
// One block per (batch, channel, face); face is innermost in the grid so
// sibling faces of a group are L2-co-resident. No smem, no barriers.
// Border cells gather from global input via a precomputed offset table.

constexpr int NBORDER = 528;          // border cells per face
constexpr int PLANE_OUT = 4624;       // 68*68

// per (face, border-cell): .x dst offset (within out group)
//                          .y src0 offset (within in group)
//                          .z src1 offset | blend<<31
//                          .w unused
__device__ uint4 hpx_tab[12 * NBORDER];

__global__ void __launch_bounds__(256) hpx_build_tab()
{
    int e = blockIdx.x * 256 + threadIdx.x;
    if (e >= 12 * NBORDER) return;

    int f = e / NBORDER;
    unsigned k = (unsigned)(e - f * NBORDER);

    int r, c;
    if (k < 136u) {
        r = (int)(k / 68u); c = (int)(k - (unsigned)r * 68u);
    } else if (k < 272u) {
        unsigned m = k - 136u;
        int mr = (int)(m / 68u);
        r = 66 + mr; c = (int)(m - (unsigned)mr * 68u);
    } else {
        unsigned m = k - 272u;
        r = 2 + (int)(m >> 2);
        int q = (int)(m & 3u);
        c = (q < 2) ? q : q + 64;
    }

    int typ = f >> 2, n = f & 3;
    int ft, ftl, flf, fbl, fbo, fbr, frg, ftr;
    if (typ == 0) {
        ft  = (n + 1) & 3;  ftl = (n + 2) & 3;  flf = (n + 3) & 3;  fbl = flf;
        fbo = n + 4;        fbr = n + 8;        frg = ((n + 1) & 3) + 4;  ftr = ft;
    } else if (typ == 1) {
        ft  = n;            flf = (n + 3) & 3;  fbl = ((n + 3) & 3) + 4;
        fbo = ((n + 3) & 3) + 8;  frg = n + 8;  ftr = ((n + 1) & 3) + 4;
        ftl = -1; fbr = -1;
    } else {
        ft  = ((n + 1) & 3) + 4;  ftl = n;  flf = n + 4;
        fbl = ((n + 3) & 3) + 8;  fbo = fbl;
        fbr = ((n + 2) & 3) + 8;  frg = ((n + 1) & 3) + 8;  ftr = frg;
    }

    int rg_r = (r < 2) ? 0 : (r < 66 ? 1 : 2);
    int rg_c = (c < 2) ? 0 : (c < 66 ? 1 : 2);
    int reg  = rg_r * 3 + rg_c;

    int sf0 = 0, sr0 = 0, sc0 = 0;
    int sf1 = -1, sr1 = 0, sc1 = 0;

    switch (reg) {
    case 0:
        if (typ == 0)      { sf0 = ftl; sr0 = 1 - r;   sc0 = 1 - c; }
        else if (typ == 2) { sf0 = ftl; sr0 = 62 + r;  sc0 = 62 + c; }
        else {
            if (c > r)      { sf0 = ft;  sr0 = 62 + r;     sc0 = c - r - 1; }
            else if (c < r) { sf0 = flf; sr0 = r - c - 1;  sc0 = 62 + c; }
            else            { sf0 = ft;  sr0 = 62 + r;  sc0 = 0;
                              sf1 = flf; sr1 = 0;       sc1 = 62 + r; }
        }
        break;
    case 1:
        if (typ == 0) { sf0 = ft; sr0 = c - 2;  sc0 = 1 - r; }
        else          { sf0 = ft; sr0 = 62 + r; sc0 = c - 2; }
        break;
    case 2:
        sf0 = ftr; sr0 = 62 + r; sc0 = c - 66;
        break;
    case 3:
        if (typ == 0) { sf0 = flf; sr0 = 1 - c;  sc0 = r - 2; }
        else          { sf0 = flf; sr0 = r - 2;  sc0 = 62 + c; }
        break;
    case 5:
        if (typ == 2) { sf0 = frg; sr0 = 129 - c; sc0 = r - 2; }
        else          { sf0 = frg; sr0 = r - 2;   sc0 = c - 66; }
        break;
    case 6:
        sf0 = fbl; sr0 = r - 66; sc0 = 62 + c;
        break;
    case 7:
        if (typ == 2) { sf0 = fbo; sr0 = c - 2;  sc0 = 129 - r; }
        else          { sf0 = fbo; sr0 = r - 66; sc0 = c - 2; }
        break;
    default:
        if (typ == 0)      { sf0 = fbr; sr0 = r - 66;  sc0 = c - 66; }
        else if (typ == 2) { sf0 = fbr; sr0 = 129 - r; sc0 = 129 - c; }
        else {
            int rr = r - 66, cc = c - 66;
            if (cc < rr)      { sf0 = fbo; sr0 = rr;            sc0 = 64 - rr + cc; }
            else if (cc > rr) { sf0 = frg; sr0 = 64 - cc + rr;  sc0 = cc; }
            else              { sf0 = fbo; sr0 = rr; sc0 = 63;
                                sf1 = frg; sr1 = 63; sc1 = rr; }
        }
        break;
    }

    uint4 t;
    t.x = (unsigned)(f * 256 * PLANE_OUT + r * 68 + c);          // dst in out group
    t.y = (unsigned)(sf0 * 256 * 4096 + sr0 * 64 + sc0);          // src0 in in group
    t.z = (sf1 >= 0)
        ? ((unsigned)(sf1 * 256 * 4096 + sr1 * 64 + sc1) | 0x80000000u)
        : 0u;
    t.w = 0u;
    hpx_tab[e] = t;
}

__global__ void __launch_bounds__(256) hpx_pad_face(const float* __restrict__ in,
                                                    float* __restrict__ out)
{
    const unsigned tid = threadIdx.x;
    const unsigned blk = blockIdx.x;            // bb*3072 + ch*12 + f
    const unsigned bb  = blk / 3072u;
    const unsigned rem = blk - bb * 3072u;
    const unsigned ch  = rem / 12u;
    const unsigned f   = rem - ch * 12u;

    const unsigned plane   = bb * 3072u + f * 256u + ch;          // (b*12+f)*256+ch
    const float*   inPlane = in + (size_t)plane * 4096u;
    float*         outPlane = out + (size_t)plane * (unsigned)PLANE_OUT;

    // ---------- interior copy: 1024 float4, 4 per thread ----------
    const float4* in4 = reinterpret_cast<const float4*>(inPlane);
    #pragma unroll
    for (int kq = 0; kq < 4; kq++) {
        unsigned i   = tid + kq * 256u;          // 0..1023
        unsigned row = i >> 4;
        unsigned qc  = i & 15u;
        float4 v = in4[i];
        float2* o2 = reinterpret_cast<float2*>(outPlane + (row + 2u) * 68u + 2u + qc * 4u);
        o2[0] = make_float2(v.x, v.y);
        o2[1] = make_float2(v.z, v.w);
    }

    // ---------- border: table-driven gather from global ----------
    const float* inGroup  = in  + ((size_t)bb * 3072u + ch) * 4096u;   // + face term in table
    float*       outGroup = out + ((size_t)bb * 3072u + ch) * (unsigned)PLANE_OUT;
    const uint4* tab = hpx_tab + f * NBORDER;

    #pragma unroll
    for (unsigned e = tid; e < (unsigned)NBORDER; e += 256u) {
        uint4 t = __ldg(&tab[e]);
        float v = __ldg(inGroup + t.y);
        if (t.z & 0x80000000u)
            v = 0.5f * v + 0.5f * __ldg(inGroup + (t.z & 0x7FFFFFFFu));
        outGroup[t.x] = v;
    }
}

extern "C" void kernel_launch(void* const* d_in, const int* in_sizes, int n_in,
                              void* d_out, int out_size)
{
    const float* in = (const float*)d_in[0];
    float* out = (float*)d_out;
    hpx_build_tab<<<(12 * NBORDER + 255) / 256, 256>>>();
    hpx_pad_face<<<24576, 256>>>(in, out);
}

// round 10
// speedup vs baseline: 2.0318x; 1.0318x over previous
#include <cuda_runtime.h>

// HEALPixPadding: [8*12, 256, 64, 64] fp32, p=2 -> [96, 256, 68, 68]
// One block per (batch, channel, face), face innermost (L2 co-residency of
// gather sources). Interior: warp-coalesced float2 copy. Border: pair-packed
// table (264 uint4/face), loads issued before interior to hide latency.

constexpr int NPAIR     = 264;        // border cell-pairs per face
constexpr int PLANE_OUT = 4624;       // 68*68

// pair entry: .x dst offset within out group (first cell; second = +1)
//             .y src0 offset within in group (24b)
//             .z src1 offset within in group (24b)
//             .w blend partner offset | flag<<30 (1=blend cell0, 2=cell1), 0=none
__device__ uint4 hpx_tab[12 * NPAIR];

// cell -> (primary src, optional blend src) within (b,ch) input group.
// src encoding: face*2^20 + r*64 + c   (face plane stride = 256*4096 = 2^20)
__device__ void cellmap(int f, int r, int c, int& s0, int& s1)
{
    int typ = f >> 2, n = f & 3;
    int ft, ftl, flf, fbl, fbo, fbr, frg, ftr;
    if (typ == 0) {
        ft  = (n + 1) & 3;  ftl = (n + 2) & 3;  flf = (n + 3) & 3;  fbl = flf;
        fbo = n + 4;        fbr = n + 8;        frg = ((n + 1) & 3) + 4;  ftr = ft;
    } else if (typ == 1) {
        ft  = n;            flf = (n + 3) & 3;  fbl = ((n + 3) & 3) + 4;
        fbo = ((n + 3) & 3) + 8;  frg = n + 8;  ftr = ((n + 1) & 3) + 4;
        ftl = -1; fbr = -1;
    } else {
        ft  = ((n + 1) & 3) + 4;  ftl = n;  flf = n + 4;
        fbl = ((n + 3) & 3) + 8;  fbo = fbl;
        fbr = ((n + 2) & 3) + 8;  frg = ((n + 1) & 3) + 8;  ftr = frg;
    }

    int rg_r = (r < 2) ? 0 : (r < 66 ? 1 : 2);
    int rg_c = (c < 2) ? 0 : (c < 66 ? 1 : 2);
    int reg  = rg_r * 3 + rg_c;

    int sf0 = 0, sr0 = 0, sc0 = 0;
    int sf1 = -1, sr1 = 0, sc1 = 0;

    switch (reg) {
    case 0:
        if (typ == 0)      { sf0 = ftl; sr0 = 1 - r;   sc0 = 1 - c; }
        else if (typ == 2) { sf0 = ftl; sr0 = 62 + r;  sc0 = 62 + c; }
        else {
            if (c > r)      { sf0 = ft;  sr0 = 62 + r;     sc0 = c - r - 1; }
            else if (c < r) { sf0 = flf; sr0 = r - c - 1;  sc0 = 62 + c; }
            else            { sf0 = ft;  sr0 = 62 + r;  sc0 = 0;
                              sf1 = flf; sr1 = 0;       sc1 = 62 + r; }
        }
        break;
    case 1:
        if (typ == 0) { sf0 = ft; sr0 = c - 2;  sc0 = 1 - r; }
        else          { sf0 = ft; sr0 = 62 + r; sc0 = c - 2; }
        break;
    case 2:
        sf0 = ftr; sr0 = 62 + r; sc0 = c - 66;
        break;
    case 3:
        if (typ == 0) { sf0 = flf; sr0 = 1 - c;  sc0 = r - 2; }
        else          { sf0 = flf; sr0 = r - 2;  sc0 = 62 + c; }
        break;
    case 5:
        if (typ == 2) { sf0 = frg; sr0 = 129 - c; sc0 = r - 2; }
        else          { sf0 = frg; sr0 = r - 2;   sc0 = c - 66; }
        break;
    case 6:
        sf0 = fbl; sr0 = r - 66; sc0 = 62 + c;
        break;
    case 7:
        if (typ == 2) { sf0 = fbo; sr0 = c - 2;  sc0 = 129 - r; }
        else          { sf0 = fbo; sr0 = r - 66; sc0 = c - 2; }
        break;
    default:
        if (typ == 0)      { sf0 = fbr; sr0 = r - 66;  sc0 = c - 66; }
        else if (typ == 2) { sf0 = fbr; sr0 = 129 - r; sc0 = 129 - c; }
        else {
            int rr = r - 66, cc = c - 66;
            if (cc < rr)      { sf0 = fbo; sr0 = rr;            sc0 = 64 - rr + cc; }
            else if (cc > rr) { sf0 = frg; sr0 = 64 - cc + rr;  sc0 = cc; }
            else              { sf0 = fbo; sr0 = rr; sc0 = 63;
                                sf1 = frg; sr1 = 63; sc1 = rr; }
        }
        break;
    }

    s0 = (sf0 << 20) + sr0 * 64 + sc0;
    s1 = (sf1 >= 0) ? ((sf1 << 20) + sr1 * 64 + sc1) : -1;
}

__global__ void __launch_bounds__(256) hpx_build_tab()
{
    int e = blockIdx.x * 256 + threadIdx.x;
    if (e >= 12 * NPAIR) return;

    int f = e / NPAIR;
    int p = e - f * NPAIR;

    int r, c;
    if (p < 68)       { r = p / 34;            c = (p % 34) * 2; }
    else if (p < 136) { int q = p - 68;  r = 66 + q / 34; c = (q % 34) * 2; }
    else              { int q = p - 136; r = 2 + q / 2;   c = (q & 1) ? 66 : 0; }

    int a0, a1, b0, b1;
    cellmap(f, r, c,     a0, a1);
    cellmap(f, r, c + 1, b0, b1);

    uint4 t;
    t.x = (unsigned)(f * 256 * PLANE_OUT + r * 68 + c);
    t.y = (unsigned)a0;
    t.z = (unsigned)b0;
    t.w = 0u;
    if (a1 >= 0) t.w = (unsigned)a1 | (1u << 30);
    if (b1 >= 0) t.w = (unsigned)b1 | (2u << 30);
    hpx_tab[e] = t;
}

__global__ void __launch_bounds__(256) hpx_pad_face(const float* __restrict__ in,
                                                    float* __restrict__ out)
{
    const unsigned tid  = threadIdx.x;
    const unsigned lane = tid & 31u;
    const unsigned warp = tid >> 5;

    const unsigned blk = blockIdx.x;            // bb*3072 + ch*12 + f
    const unsigned bb  = blk / 3072u;
    const unsigned rem = blk - bb * 3072u;
    const unsigned ch  = rem / 12u;
    const unsigned f   = rem - ch * 12u;

    const float* inGroup  = in  + ((size_t)bb * 3072u + ch) * 4096u;
    float*       outGroup = out + ((size_t)bb * 3072u + ch) * (size_t)PLANE_OUT;
    const float* inPlane  = inGroup  + (size_t)f * 1048576u;        // 256*4096
    float*       outPlane = outGroup + (size_t)f * 256u * PLANE_OUT;

    // ---- border pair: issue loads FIRST (latency hides under interior) ----
    uint4 t = __ldg(&hpx_tab[f * NPAIR + tid]);               // tid < 256 < 264
    float a = __ldg(inGroup + t.y);
    float b = __ldg(inGroup + t.z);
    unsigned wflag = t.w >> 30;
    float s = 0.0f;
    if (wflag) s = __ldg(inGroup + (t.w & 0x00FFFFFFu));

    // ---- interior copy: warp-coalesced float2 rows ----
    const float2* in2 = reinterpret_cast<const float2*>(inPlane);
    float2 v[8];
    #pragma unroll
    for (int rr = 0; rr < 8; rr++) {
        unsigned row = (unsigned)rr * 8u + warp;              // 0..63
        v[rr] = in2[row * 32u + lane];
    }
    #pragma unroll
    for (int rr = 0; rr < 8; rr++) {
        unsigned row = (unsigned)rr * 8u + warp;
        *reinterpret_cast<float2*>(outPlane + (row + 2u) * 68u + 2u + 2u * lane) = v[rr];
    }

    // ---- border pair: blend + coalesced 8B store ----
    if (wflag == 1u)      a = 0.5f * a + 0.5f * s;
    else if (wflag == 2u) b = 0.5f * b + 0.5f * s;
    *reinterpret_cast<float2*>(outGroup + t.x) = make_float2(a, b);

    // ---- leftover 8 pairs (e = 256..263) ----
    if (tid < 8u) {
        uint4 t2 = __ldg(&hpx_tab[f * NPAIR + 256u + tid]);
        float a2 = __ldg(inGroup + t2.y);
        float b2 = __ldg(inGroup + t2.z);
        unsigned w2 = t2.w >> 30;
        if (w2) {
            float s2 = __ldg(inGroup + (t2.w & 0x00FFFFFFu));
            if (w2 == 1u) a2 = 0.5f * a2 + 0.5f * s2;
            else          b2 = 0.5f * b2 + 0.5f * s2;
        }
        *reinterpret_cast<float2*>(outGroup + t2.x) = make_float2(a2, b2);
    }
}

extern "C" void kernel_launch(void* const* d_in, const int* in_sizes, int n_in,
                              void* d_out, int out_size)
{
    const float* in = (const float*)d_in[0];
    float* out = (float*)d_out;
    hpx_build_tab<<<(12 * NPAIR + 255) / 256, 256>>>();
    hpx_pad_face<<<24576, 256>>>(in, out);
}